// round 1
// baseline (speedup 1.0000x reference)
#include <cuda_runtime.h>

// GraphAttention fused kernel, fp32 FFMA baseline.
// One CTA per batch element. h and alpha live in SMEM; x is streamed in K-tiles.
//
// Phase 1: h[128][256] = x_b[128][512] @ W_w^T + W_b   (SMEM-tiled GEMM, KC=32)
// Phase 2: f,g = h@a_src, h@a_dst; alpha = softmax_i(lrelu(f_i+g_j+ab))
// Phase 3: out_b = alpha[128][128] @ h[128][256]

#define B_    256
#define C_    128
#define T_    512
#define H_    256
#define KC    32
#define HS    260   // h row stride (pad: bank-conflict-free column walks)
#define AS    132   // alpha / xt row stride

// SMEM layout (floats):
//  [0, C_*HS)                      : h
//  [C_*HS, C_*HS + C_*AS)          : alpha  (phase 2/3)  -- overlaps xt/wt staging (phase 1)
//      staging: xt[KC][AS] then wt[KC][HS]  (12544 floats <= 16896)
//  then fv[128], gv[128], csum[256], inv[128]
#define SM_FLOATS (C_*HS + C_*AS + 4*C_ + C_)
#define SMEM_BYTES (SM_FLOATS * 4)

__global__ __launch_bounds__(256, 1)
void gat_fused_kernel(const float* __restrict__ x,
                      const float* __restrict__ Ww,
                      const float* __restrict__ Wb,
                      const float* __restrict__ aw,
                      const float* __restrict__ ab,
                      float* __restrict__ out)
{
    extern __shared__ float sm[];
    float* h      = sm;                  // C_*HS
    float* shared2= sm + C_*HS;
    float* alpha  = shared2;             // C_*AS
    float* xt     = shared2;             // KC*AS  (phase-1 staging, overlaps alpha)
    float* wt     = shared2 + KC*AS;     // KC*HS
    float* fv     = shared2 + C_*AS;     // 128
    float* gv     = fv + C_;             // 128
    float* csum   = gv + C_;             // 256
    float* inv    = csum + 2*C_;         // 128

    const int b   = blockIdx.x;
    const int tid = threadIdx.x;
    const int tx  = tid & 15;            // 0..15 -> output columns
    const int ty  = tid >> 4;            // 0..15 -> output rows

    const float* xb = x + (size_t)b * C_ * T_;

    float acc[8][16];
    #pragma unroll
    for (int r = 0; r < 8; r++)
        #pragma unroll
        for (int c = 0; c < 16; c++) acc[r][c] = 0.f;

    // ------------------- Phase 1: h = x @ Ww^T -------------------
    const int kk0 = (tid & 7) * 4;       // which 4 k's this thread stages
    const int rr  = tid >> 3;            // 0..31 staging row

    for (int k0 = 0; k0 < T_; k0 += KC) {
        // stage x tile (128 x 32), store k-major (transposed)
        #pragma unroll
        for (int it = 0; it < 4; it++) {
            int c = rr + it * 32;
            float4 v = *(const float4*)(xb + c * T_ + k0 + kk0);
            xt[(kk0+0)*AS + c] = v.x;
            xt[(kk0+1)*AS + c] = v.y;
            xt[(kk0+2)*AS + c] = v.z;
            xt[(kk0+3)*AS + c] = v.w;
        }
        // stage W tile (256 x 32), store k-major
        #pragma unroll
        for (int it = 0; it < 8; it++) {
            int j = rr + it * 32;
            float4 v = *(const float4*)(Ww + j * T_ + k0 + kk0);
            wt[(kk0+0)*HS + j] = v.x;
            wt[(kk0+1)*HS + j] = v.y;
            wt[(kk0+2)*HS + j] = v.z;
            wt[(kk0+3)*HS + j] = v.w;
        }
        __syncthreads();

        #pragma unroll 4
        for (int k = 0; k < KC; k++) {
            float a[8];
            #pragma unroll
            for (int r = 0; r < 8; r++) a[r] = xt[k*AS + ty*8 + r];
            float bb[16];
            #pragma unroll
            for (int ch = 0; ch < 4; ch++) {
                float4 v = *(const float4*)(wt + k*HS + ch*64 + tx*4);
                bb[ch*4+0] = v.x; bb[ch*4+1] = v.y;
                bb[ch*4+2] = v.z; bb[ch*4+3] = v.w;
            }
            #pragma unroll
            for (int r = 0; r < 8; r++)
                #pragma unroll
                for (int c = 0; c < 16; c++)
                    acc[r][c] += a[r] * bb[c];
        }
        __syncthreads();
    }

    // bias add, store h to SMEM
    #pragma unroll
    for (int ch = 0; ch < 4; ch++) {
        int c0 = ch*64 + tx*4;
        float4 bias = *(const float4*)(Wb + c0);
        #pragma unroll
        for (int r = 0; r < 8; r++) {
            int i = ty*8 + r;
            float4 hv;
            hv.x = acc[r][ch*4+0] + bias.x;
            hv.y = acc[r][ch*4+1] + bias.y;
            hv.z = acc[r][ch*4+2] + bias.z;
            hv.w = acc[r][ch*4+3] + bias.w;
            *(float4*)(h + i*HS + c0) = hv;
        }
    }
    __syncthreads();

    // ------------------- Phase 2: f, g, softmax over i -------------------
    if (tid < C_) {
        float f_ = 0.f, g_ = 0.f;
        #pragma unroll 8
        for (int j = 0; j < H_; j += 4) {
            float4 hv  = *(const float4*)(h + tid*HS + j);
            float4 as_ = *(const float4*)(aw + j);
            float4 ad_ = *(const float4*)(aw + H_ + j);
            f_ += hv.x*as_.x + hv.y*as_.y + hv.z*as_.z + hv.w*as_.w;
            g_ += hv.x*ad_.x + hv.y*ad_.y + hv.z*ad_.z + hv.w*ad_.w;
        }
        fv[tid] = f_;
        gv[tid] = g_;
    }
    __syncthreads();

    {
        int j    = tid & 127;
        int part = tid >> 7;          // 0 or 1 -> which i-half
        float gj  = gv[j];
        float abv = ab[0];
        float s = 0.f;
        int i0 = part * 64;
        #pragma unroll 4
        for (int i = i0; i < i0 + 64; i++) {
            float z = fv[i] + gj + abv;
            z = (z > 0.f) ? z : 0.2f * z;      // leaky_relu slope 0.2
            float ex = __expf(z);
            alpha[i*AS + j] = ex;
            s += ex;
        }
        csum[part*C_ + j] = s;
    }
    __syncthreads();
    if (tid < C_) inv[tid] = 1.0f / (csum[tid] + csum[C_ + tid]);
    __syncthreads();
    {
        int j    = tid & 127;
        int part = tid >> 7;
        float iv = inv[j];
        int i0 = part * 64;
        #pragma unroll 8
        for (int i = i0; i < i0 + 64; i++)
            alpha[i*AS + j] *= iv;
    }
    __syncthreads();

    // ------------------- Phase 3: out = alpha @ h -------------------
    #pragma unroll
    for (int r = 0; r < 8; r++)
        #pragma unroll
        for (int c = 0; c < 16; c++) acc[r][c] = 0.f;

    #pragma unroll 4
    for (int k = 0; k < C_; k++) {
        float a[8];
        #pragma unroll
        for (int r = 0; r < 8; r++) a[r] = alpha[(ty*8 + r)*AS + k];
        float bb[16];
        #pragma unroll
        for (int ch = 0; ch < 4; ch++) {
            float4 v = *(const float4*)(h + k*HS + ch*64 + tx*4);
            bb[ch*4+0] = v.x; bb[ch*4+1] = v.y;
            bb[ch*4+2] = v.z; bb[ch*4+3] = v.w;
        }
        #pragma unroll
        for (int r = 0; r < 8; r++)
            #pragma unroll
            for (int c = 0; c < 16; c++)
                acc[r][c] += a[r] * bb[c];
    }

    float* ob = out + (size_t)b * C_ * H_;
    #pragma unroll
    for (int ch = 0; ch < 4; ch++) {
        int c0 = ch*64 + tx*4;
        #pragma unroll
        for (int r = 0; r < 8; r++) {
            int i = ty*8 + r;
            float4 v;
            v.x = acc[r][ch*4+0];
            v.y = acc[r][ch*4+1];
            v.z = acc[r][ch*4+2];
            v.w = acc[r][ch*4+3];
            *(float4*)(ob + i*H_ + c0) = v;
        }
    }
}

extern "C" void kernel_launch(void* const* d_in, const int* in_sizes, int n_in,
                              void* d_out, int out_size)
{
    const float* x  = (const float*)d_in[0];
    const float* Ww = (const float*)d_in[1];
    const float* Wb = (const float*)d_in[2];
    const float* aw = (const float*)d_in[3];
    const float* ab = (const float*)d_in[4];
    float* out = (float*)d_out;

    // idempotent, host-side only (not a stream op; safe under graph capture)
    cudaFuncSetAttribute(gat_fused_kernel,
                         cudaFuncAttributeMaxDynamicSharedMemorySize, SMEM_BYTES);

    gat_fused_kernel<<<B_, 256, SMEM_BYTES>>>(x, Ww, Wb, aw, ab, out);
}

// round 3
// speedup vs baseline: 2.8791x; 2.8791x over previous
#include <cuda_runtime.h>
#include <cstdint>

// GraphAttention fused, mma.sync tf32 tensor-core version (sm_100-compatible PTX).
// One CTA per batch. Phase1: h = x @ Ww^T + Wb (128x256x512, tf32 mma, cp.async
// double-buffered staging). Phase2: softmax in SMEM. Phase3: out = alpha @ h
// (128x256x128, tf32 mma). fp32 accumulate throughout.

#define B_ 256
#define C_ 128
#define T_ 512
#define H_ 256
#define KC 32
#define CHUNKS 16

// SMEM float offsets
#define XSTR 36
#define WSTR 36
#define HSTR 264
#define ASTR 132
#define STAGE_F 13824            // per-stage floats: x 128*36 + W 256*36
#define WOFF 4608                // W tile offset within a stage
#define ALPHA_F 33792            // h region: 128*264 = 33792 floats (aliases stages)
#define MISC_F  (ALPHA_F + 16896)
// misc sub-offsets (floats from misc base)
#define M_WB   0
#define M_ASRC 256
#define M_ADST 512
#define M_FP   768
#define M_GP   1024
#define M_FV   1280
#define M_GV   1408
#define M_SP   1536
#define M_SINV 1792
#define M_AB   1920
#define SM_FLOATS (MISC_F + 2048)
#define SMEM_BYTES (SM_FLOATS * 4)

__device__ __forceinline__ uint32_t smem_u32(const void* p) {
    uint32_t a;
    asm("{ .reg .u64 t; cvta.to.shared.u64 t, %1; cvt.u32.u64 %0, t; }" : "=r"(a) : "l"(p));
    return a;
}

#define CP_ASYNC16(dst_u32, src_ptr) \
    asm volatile("cp.async.cg.shared.global [%0], [%1], 16;" :: "r"(dst_u32), "l"(src_ptr) : "memory")
#define CP_COMMIT() asm volatile("cp.async.commit_group;" ::: "memory")
#define CP_WAIT(n)  asm volatile("cp.async.wait_group %0;" :: "n"(n) : "memory")

__device__ __forceinline__ uint32_t f2tf(float x) {
    uint32_t r;
    asm("cvt.rna.tf32.f32 %0, %1;" : "=r"(r) : "f"(x));
    return r;
}

__device__ __forceinline__ void mma8(float* c, const uint32_t* a, const uint32_t* b) {
    asm volatile(
        "mma.sync.aligned.m16n8k8.row.col.f32.tf32.tf32.f32 "
        "{%0,%1,%2,%3}, {%4,%5,%6,%7}, {%8,%9}, {%0,%1,%2,%3};"
        : "+f"(c[0]), "+f"(c[1]), "+f"(c[2]), "+f"(c[3])
        : "r"(a[0]), "r"(a[1]), "r"(a[2]), "r"(a[3]), "r"(b[0]), "r"(b[1]));
}

__global__ __launch_bounds__(256, 1)
void gat_mma_kernel(const float* __restrict__ x,
                    const float* __restrict__ Ww,
                    const float* __restrict__ Wb,
                    const float* __restrict__ aw,
                    const float* __restrict__ ab,
                    float* __restrict__ out)
{
    extern __shared__ float sm[];
    float* hsm   = sm;                 // stride HSTR, 128 rows (aliases stages)
    float* alpha = sm + ALPHA_F;       // stride ASTR, 128 rows
    float* misc  = sm + MISC_F;

    const int tid  = threadIdx.x;
    const int lane = tid & 31;
    const int warp = tid >> 5;
    const int wr   = warp >> 2;        // 0..1: row block (64 rows)
    const int wc   = warp & 3;         // 0..3: col block (64 cols)
    const int b    = blockIdx.x;

    const float* xb = x + (size_t)b * C_ * T_;

    // param preload
    misc[M_WB + tid]   = Wb[tid];
    misc[M_ASRC + tid] = aw[tid];
    misc[M_ADST + tid] = aw[H_ + tid];
    if (tid == 0) misc[M_AB] = ab[0];

    const uint32_t stage_u32 = smem_u32(sm);

    // staging: chunk c -> stage s (row-major, k-contiguous, stride 36)
    auto issue_chunk = [&](int c, int s) {
        uint32_t base = stage_u32 + (uint32_t)s * (STAGE_F * 4);
        const float* xsrc = xb + c * KC;
        #pragma unroll
        for (int i = 0; i < 4; i++) {
            int idx = tid + i * 256;               // < 1024
            int row = idx >> 3, slot = idx & 7;
            CP_ASYNC16(base + (uint32_t)(row * XSTR + slot * 4) * 4,
                       xsrc + row * T_ + slot * 4);
        }
        const float* wsrc = Ww + c * KC;
        #pragma unroll
        for (int i = 0; i < 8; i++) {
            int idx = tid + i * 256;               // < 2048
            int row = idx >> 3, slot = idx & 7;
            CP_ASYNC16(base + (uint32_t)(WOFF + row * WSTR + slot * 4) * 4,
                       wsrc + row * T_ + slot * 4);
        }
        CP_COMMIT();
    };

    issue_chunk(0, 0);
    issue_chunk(1, 1);

    float acc[4][8][4];
    #pragma unroll
    for (int mb = 0; mb < 4; mb++)
        #pragma unroll
        for (int nb = 0; nb < 8; nb++)
            #pragma unroll
            for (int q = 0; q < 4; q++) acc[mb][nb][q] = 0.f;

    const int lq = lane >> 2;   // 0..7
    const int lk = lane & 3;    // 0..3

    // ---- Phase 1: h = x @ Ww^T ----
    for (int c = 0; c < CHUNKS; c++) {
        if (c < CHUNKS - 2) CP_WAIT(1); else CP_WAIT(0);
        __syncthreads();

        const float* xs = sm + (c & 1) * STAGE_F;
        const float* ws = xs + WOFF;

        #pragma unroll
        for (int kq = 0; kq < 4; kq++) {
            const int k0 = kq * 8;
            uint32_t afr[4][4];
            #pragma unroll
            for (int mb = 0; mb < 4; mb++) {
                int r = wr * 64 + mb * 16 + lq;
                afr[mb][0] = f2tf(xs[r * XSTR + k0 + lk]);
                afr[mb][1] = f2tf(xs[(r + 8) * XSTR + k0 + lk]);
                afr[mb][2] = f2tf(xs[r * XSTR + k0 + 4 + lk]);
                afr[mb][3] = f2tf(xs[(r + 8) * XSTR + k0 + 4 + lk]);
            }
            uint32_t bfr[8][2];
            #pragma unroll
            for (int nb = 0; nb < 8; nb++) {
                int j = wc * 64 + nb * 8 + lq;
                bfr[nb][0] = f2tf(ws[j * WSTR + k0 + lk]);
                bfr[nb][1] = f2tf(ws[j * WSTR + k0 + 4 + lk]);
            }
            #pragma unroll
            for (int mb = 0; mb < 4; mb++)
                #pragma unroll
                for (int nb = 0; nb < 8; nb++)
                    mma8(acc[mb][nb], afr[mb], bfr[nb]);
        }
        __syncthreads();
        if (c + 2 < CHUNKS) issue_chunk(c + 2, c & 1);
    }

    // ---- Epilogue 1: h = acc + bias -> SMEM (stride 264) ----
    #pragma unroll
    for (int mb = 0; mb < 4; mb++) {
        int r  = wr * 64 + mb * 16 + lq;
        int r2 = r + 8;
        #pragma unroll
        for (int nb = 0; nb < 8; nb++) {
            int j0 = wc * 64 + nb * 8 + 2 * lk;
            float b0 = misc[M_WB + j0], b1 = misc[M_WB + j0 + 1];
            float2 v0 = make_float2(acc[mb][nb][0] + b0, acc[mb][nb][1] + b1);
            float2 v1 = make_float2(acc[mb][nb][2] + b0, acc[mb][nb][3] + b1);
            *(float2*)&hsm[r  * HSTR + j0] = v0;
            *(float2*)&hsm[r2 * HSTR + j0] = v1;
        }
    }
    __syncthreads();

    // ---- f, g ----
    {
        const int row = tid & 127, half = tid >> 7;
        float f_ = 0.f, g_ = 0.f;
        const int j0 = half * 128;
        #pragma unroll 8
        for (int jj = 0; jj < 128; jj += 4) {
            int j = j0 + jj;
            float4 hv = *(const float4*)&hsm[row * HSTR + j];
            float4 as_ = *(const float4*)&misc[M_ASRC + j];
            float4 ad_ = *(const float4*)&misc[M_ADST + j];
            f_ += hv.x * as_.x + hv.y * as_.y + hv.z * as_.z + hv.w * as_.w;
            g_ += hv.x * ad_.x + hv.y * ad_.y + hv.z * ad_.z + hv.w * ad_.w;
        }
        misc[M_FP + half * 128 + row] = f_;
        misc[M_GP + half * 128 + row] = g_;
    }
    __syncthreads();
    if (tid < 128) {
        misc[M_FV + tid] = misc[M_FP + tid] + misc[M_FP + 128 + tid];
        misc[M_GV + tid] = misc[M_GP + tid] + misc[M_GP + 128 + tid];
    }
    __syncthreads();

    // ---- Phase 2: softmax over i ----
    {
        const int j = tid & 127, half = tid >> 7;
        const float gj = misc[M_GV + j] + misc[M_AB];
        float s = 0.f;
        const int i0 = half * 64;
        #pragma unroll 4
        for (int i = i0; i < i0 + 64; i++) {
            float z = misc[M_FV + i] + gj;
            z = (z > 0.f) ? z : 0.2f * z;
            float ex = __expf(z);
            alpha[i * ASTR + j] = ex;
            s += ex;
        }
        misc[M_SP + half * 128 + j] = s;
        __syncthreads();
        if (tid < 128)
            misc[M_SINV + tid] = 1.0f / (misc[M_SP + tid] + misc[M_SP + 128 + tid]);
        __syncthreads();
        const float iv = misc[M_SINV + j];
        #pragma unroll 8
        for (int i = i0; i < i0 + 64; i++)
            alpha[i * ASTR + j] *= iv;
    }
    __syncthreads();

    // ---- Phase 3: out = alpha @ h ----
    #pragma unroll
    for (int mb = 0; mb < 4; mb++)
        #pragma unroll
        for (int nb = 0; nb < 8; nb++)
            #pragma unroll
            for (int q = 0; q < 4; q++) acc[mb][nb][q] = 0.f;

    #pragma unroll 4
    for (int kq = 0; kq < 16; kq++) {
        const int k0 = kq * 8;
        uint32_t afr[4][4];
        #pragma unroll
        for (int mb = 0; mb < 4; mb++) {
            int r = wr * 64 + mb * 16 + lq;
            afr[mb][0] = f2tf(alpha[r * ASTR + k0 + lk]);
            afr[mb][1] = f2tf(alpha[(r + 8) * ASTR + k0 + lk]);
            afr[mb][2] = f2tf(alpha[r * ASTR + k0 + 4 + lk]);
            afr[mb][3] = f2tf(alpha[(r + 8) * ASTR + k0 + 4 + lk]);
        }
        uint32_t bfr[8][2];
        #pragma unroll
        for (int nb = 0; nb < 8; nb++) {
            int j = wc * 64 + nb * 8 + lq;
            bfr[nb][0] = f2tf(hsm[(k0 + lk) * HSTR + j]);
            bfr[nb][1] = f2tf(hsm[(k0 + 4 + lk) * HSTR + j]);
        }
        #pragma unroll
        for (int mb = 0; mb < 4; mb++)
            #pragma unroll
            for (int nb = 0; nb < 8; nb++)
                mma8(acc[mb][nb], afr[mb], bfr[nb]);
    }

    // ---- Epilogue 2: store out ----
    {
        float* ob = out + (size_t)b * C_ * H_;
        #pragma unroll
        for (int mb = 0; mb < 4; mb++) {
            int r  = wr * 64 + mb * 16 + lq;
            int r2 = r + 8;
            #pragma unroll
            for (int nb = 0; nb < 8; nb++) {
                int j0 = wc * 64 + nb * 8 + 2 * lk;
                *(float2*)&ob[r  * H_ + j0] = make_float2(acc[mb][nb][0], acc[mb][nb][1]);
                *(float2*)&ob[r2 * H_ + j0] = make_float2(acc[mb][nb][2], acc[mb][nb][3]);
            }
        }
    }
}

extern "C" void kernel_launch(void* const* d_in, const int* in_sizes, int n_in,
                              void* d_out, int out_size)
{
    const float* x  = (const float*)d_in[0];
    const float* Ww = (const float*)d_in[1];
    const float* Wb = (const float*)d_in[2];
    const float* aw = (const float*)d_in[3];
    const float* ab = (const float*)d_in[4];
    float* out = (float*)d_out;

    cudaFuncSetAttribute(gat_mma_kernel,
                         cudaFuncAttributeMaxDynamicSharedMemorySize, SMEM_BYTES);

    gat_mma_kernel<<<B_, 256, SMEM_BYTES>>>(x, Ww, Wb, aw, ab, out);
}